// round 1
// baseline (speedup 1.0000x reference)
#include <cuda_runtime.h>
#include <cuda_fp16.h>
#include <stdint.h>

#define B 4
#define S 2048
#define H 8
#define E 64
#define BH (B*H)

#define TQ 16        // queries per CTA (attention kernel)
#define KT 256       // phase-1 K tile rows
#define VT 128       // phase-3 V tile rows
#define EP 68        // padded smem row (bank-conflict-free)
#define PROJ_TOK 32  // tokens per CTA (projection kernel)

// Scratch for projected Q,K,V in [B,H,S,E] layout (device globals: allocation-free)
__device__ float g_q[(size_t)BH*S*E];
__device__ float g_k[(size_t)BH*S*E];
__device__ float g_v[(size_t)BH*S*E];

// ---------------------------------------------------------------------------
// Threefry2x32, JAX partitionable variant:
//   bits(i) = out0 ^ out1 of threefry2x32(key=(0,42), x=(hi32(i), lo32(i)))
// n = 2^27 < 2^32 so hi word is always 0.
// ---------------------------------------------------------------------------
__device__ __forceinline__ uint32_t rotl32(uint32_t v, int s) {
    return __funnelshift_l(v, v, s);
}

__device__ __forceinline__ uint32_t threefry_mask_bits(uint32_t idx) {
    const uint32_t ks0 = 0u;
    const uint32_t ks1 = 42u;
    const uint32_t ks2 = 0x1BD11BDAu ^ 0u ^ 42u;
    uint32_t x0 = 0u + ks0;
    uint32_t x1 = idx + ks1;
#define TFR(r) { x0 += x1; x1 = rotl32(x1, r); x1 ^= x0; }
    TFR(13) TFR(15) TFR(26) TFR(6)
    x0 += ks1; x1 += ks2 + 1u;
    TFR(17) TFR(29) TFR(16) TFR(24)
    x0 += ks2; x1 += ks0 + 2u;
    TFR(13) TFR(15) TFR(26) TFR(6)
    x0 += ks0; x1 += ks1 + 3u;
    TFR(17) TFR(29) TFR(16) TFR(24)
    x0 += ks1; x1 += ks2 + 4u;
    TFR(13) TFR(15) TFR(26) TFR(6)
    x0 += ks2; x1 += ks0 + 5u;
#undef TFR
    return x0 ^ x1;
}

// keep ⟺ uniform(bits) < 0.9f ⟺ (bits>>9) < 7549747  (0.9f == 7549747 * 2^-23 exactly)
__device__ __forceinline__ bool dropout_keep(uint32_t bits) {
    return (bits >> 9) < 7549747u;
}

// ---------------------------------------------------------------------------
// Kernel 1: QKV projection.  grid = (tokens/PROJ_TOK, 3), 256 threads.
// out[f] = b[f] + sum_e x[e] * W[f][e];  written to [B,H,S,E] layout.
// ---------------------------------------------------------------------------
__global__ __launch_bounds__(256) void proj_kernel(
    const float* __restrict__ qin, const float* __restrict__ kin, const float* __restrict__ vin,
    const float* __restrict__ Wq, const float* __restrict__ bq,
    const float* __restrict__ Wk, const float* __restrict__ bk,
    const float* __restrict__ Wv, const float* __restrict__ bv)
{
    __shared__ float sW[64][EP];
    __shared__ float sb[64];
    __shared__ float sx[PROJ_TOK][64];

    const int m = blockIdx.y;
    const float* __restrict__ xin  = (m == 0) ? qin : ((m == 1) ? kin : vin);
    const float* __restrict__ W    = (m == 0) ? Wq  : ((m == 1) ? Wk  : Wv);
    const float* __restrict__ bias = (m == 0) ? bq  : ((m == 1) ? bk  : bv);
    float* __restrict__ dst        = (m == 0) ? g_q : ((m == 1) ? g_k : g_v);

    const int tid = threadIdx.x;
    const size_t tok0 = (size_t)blockIdx.x * PROJ_TOK;

    for (int i = tid; i < 64 * 16; i += 256) {
        int r = i >> 4, c = i & 15;
        float4 w = ((const float4*)W)[i];
        ((float4*)(&sW[r][0]))[c] = w;
    }
    if (tid < 64) sb[tid] = bias[tid];
    for (int i = tid; i < PROJ_TOK * 16; i += 256) {
        ((float4*)(&sx[0][0]))[i] = ((const float4*)(xin + tok0 * 64))[i];
    }
    __syncthreads();

    const int f  = tid & 63;
    const int tg = tid >> 6;  // 0..3

    float4 wr[16];
    #pragma unroll
    for (int e4 = 0; e4 < 16; e4++) wr[e4] = ((float4*)(&sW[f][0]))[e4];
    const float bsv = sb[f];

    for (int tt = 0; tt < PROJ_TOK; tt += 4) {
        const int t = tt + tg;
        float acc = bsv;
        #pragma unroll
        for (int e4 = 0; e4 < 16; e4++) {
            float4 xv = ((float4*)(&sx[t][0]))[e4];
            acc += xv.x * wr[e4].x + xv.y * wr[e4].y + xv.z * wr[e4].z + xv.w * wr[e4].w;
        }
        const size_t tok = tok0 + t;            // tok = (b*S + s)*H + h
        const int b   = (int)(tok >> 14);       // S*H = 16384
        const int rem = (int)(tok & 16383);
        const int s   = rem >> 3;               // H = 8
        const int h   = rem & 7;
        dst[(((size_t)(b * H + h)) * S + s) * 64 + f] = acc;
    }
}

// ---------------------------------------------------------------------------
// Kernel 2: fused attention.  grid = (S/TQ, BH), 256 threads, 1 CTA/SM.
// Phase 1: scores = (Q*0.125) @ K^T into smem (TQ x S fp32)
// Phase 2: rowwise softmax + threefry dropout + fp16 round (in-place)
// Phase 3: out = attn @ V  (split-k over 4 thread groups, smem reduce)
// ---------------------------------------------------------------------------
// dynamic smem: sc[TQ*S] | ks[KT*EP] | qs[TQ*64]  = 204800 bytes
#define SMEM_BYTES ((TQ*S + KT*EP + TQ*64) * 4)

__global__ __launch_bounds__(256, 1) void attn_kernel(float* __restrict__ out)
{
    extern __shared__ float smem[];
    float* sc = smem;               // [TQ][S]
    float* ks = smem + TQ * S;      // [KT][EP]
    float* qs = ks + KT * EP;       // [TQ][64]

    const int tid = threadIdx.x;
    const int bh  = blockIdx.y;
    const int q0  = blockIdx.x * TQ;

    const float* __restrict__ qg = g_q + (size_t)bh * S * E + (size_t)q0 * E;
    const float* __restrict__ kg = g_k + (size_t)bh * S * E;
    const float* __restrict__ vg = g_v + (size_t)bh * S * E;

    // load Q tile, pre-scaled by 1/sqrt(E) (exact power of 2)
    for (int i = tid; i < TQ * 16; i += 256) {
        float4 v = ((const float4*)qg)[i];
        v.x *= 0.125f; v.y *= 0.125f; v.z *= 0.125f; v.w *= 0.125f;
        ((float4*)qs)[i] = v;
    }

    // ------------------ Phase 1: scores ------------------
    const int qid = tid >> 6;   // 0..3 -> q rows qid*4 .. qid*4+3
    const int kid = tid & 63;   // 0..63 -> k cols kid + 64*j

    for (int kt = 0; kt < S; kt += KT) {
        __syncthreads();
        for (int i = tid; i < KT * 16; i += 256) {
            int r = i >> 4, c = i & 15;
            ((float4*)(ks + r * EP))[c] = ((const float4*)(kg + (size_t)(kt + r) * E))[c];
        }
        __syncthreads();

        float acc[4][4];
        #pragma unroll
        for (int i = 0; i < 4; i++)
            #pragma unroll
            for (int j = 0; j < 4; j++) acc[i][j] = 0.0f;

        #pragma unroll
        for (int e4 = 0; e4 < 16; e4++) {
            float4 qv[4], kv[4];
            #pragma unroll
            for (int i = 0; i < 4; i++) qv[i] = ((float4*)(qs + (qid * 4 + i) * 64))[e4];
            #pragma unroll
            for (int j = 0; j < 4; j++) kv[j] = ((float4*)(ks + (kid + 64 * j) * EP))[e4];
            #pragma unroll
            for (int i = 0; i < 4; i++)
                #pragma unroll
                for (int j = 0; j < 4; j++)
                    acc[i][j] += qv[i].x * kv[j].x + qv[i].y * kv[j].y +
                                 qv[i].z * kv[j].z + qv[i].w * kv[j].w;
        }

        #pragma unroll
        for (int i = 0; i < 4; i++)
            #pragma unroll
            for (int j = 0; j < 4; j++)
                sc[(qid * 4 + i) * S + kt + kid + 64 * j] = acc[i][j];
    }
    __syncthreads();

    // ------------------ Phase 2: softmax + dropout + fp16 ------------------
    {
        const int warp = tid >> 5, lane = tid & 31;
        for (int r = warp; r < TQ; r += 8) {
            float* row = sc + r * S;
            float mx = -1e30f;
            for (int i = lane; i < S; i += 32) mx = fmaxf(mx, row[i]);
            #pragma unroll
            for (int o = 16; o; o >>= 1) mx = fmaxf(mx, __shfl_xor_sync(0xffffffffu, mx, o));

            float sum = 0.0f;
            for (int i = lane; i < S; i += 32) {
                float ev = expf(row[i] - mx);
                row[i] = ev;
                sum += ev;
            }
            #pragma unroll
            for (int o = 16; o; o >>= 1) sum += __shfl_xor_sync(0xffffffffu, sum, o);
            const float inv = 1.0f / sum;

            const uint32_t base = (uint32_t)(bh * S + q0 + r) * (uint32_t)S;
            for (int i = lane; i < S; i += 32) {
                float a = row[i] * inv;
                uint32_t bits = threefry_mask_bits(base + (uint32_t)i);
                a = dropout_keep(bits) ? a * (1.0f / 0.9f) : 0.0f;
                a = __half2float(__float2half_rn(a));   // explicit fp16 round as in reference
                row[i] = a;
            }
        }
    }

    // ------------------ Phase 3: out = attn @ V ------------------
    const int g   = tid >> 6;          // split-k group 0..3
    const int t64 = tid & 63;
    const int oq  = (t64 >> 4) * 4;    // q base (0,4,8,12)
    const int oe  = (t64 & 15) * 4;    // e base (0..60)

    float oacc[4][4];
    #pragma unroll
    for (int i = 0; i < 4; i++)
        #pragma unroll
        for (int j = 0; j < 4; j++) oacc[i][j] = 0.0f;

    for (int vt = 0; vt < S; vt += VT) {
        __syncthreads();
        for (int i = tid; i < VT * 16; i += 256) {
            int r = i >> 4, c = i & 15;
            ((float4*)(ks + r * EP))[c] = ((const float4*)(vg + (size_t)(vt + r) * E))[c];
        }
        __syncthreads();

        #pragma unroll
        for (int kk = 0; kk < 32; kk += 4) {
            const int k = g * 32 + kk;
            float4 av[4];
            #pragma unroll
            for (int i = 0; i < 4; i++) av[i] = *(float4*)(sc + (oq + i) * S + vt + k);
            float4 vv[4];
            #pragma unroll
            for (int j = 0; j < 4; j++) vv[j] = *(float4*)(ks + (k + j) * EP + oe);
            #pragma unroll
            for (int i = 0; i < 4; i++) {
                oacc[i][0] += av[i].x * vv[0].x + av[i].y * vv[1].x + av[i].z * vv[2].x + av[i].w * vv[3].x;
                oacc[i][1] += av[i].x * vv[0].y + av[i].y * vv[1].y + av[i].z * vv[2].y + av[i].w * vv[3].y;
                oacc[i][2] += av[i].x * vv[0].z + av[i].y * vv[1].z + av[i].z * vv[2].z + av[i].w * vv[3].z;
                oacc[i][3] += av[i].x * vv[0].w + av[i].y * vv[1].w + av[i].z * vv[2].w + av[i].w * vv[3].w;
            }
        }
    }

    // split-k reduction through smem (reuse sc), group 0 writes output
    __syncthreads();
    if (g != 0) {
        float* red = sc + (g - 1) * (TQ * E);
        #pragma unroll
        for (int i = 0; i < 4; i++)
            *(float4*)(red + (oq + i) * E + oe) =
                make_float4(oacc[i][0], oacc[i][1], oacc[i][2], oacc[i][3]);
    }
    __syncthreads();
    if (g == 0) {
        float* og = out + ((size_t)bh * S + q0) * E;
        #pragma unroll
        for (int i = 0; i < 4; i++) {
            float4 r0 = *(float4*)(sc + 0 * (TQ * E) + (oq + i) * E + oe);
            float4 r1 = *(float4*)(sc + 1 * (TQ * E) + (oq + i) * E + oe);
            float4 r2 = *(float4*)(sc + 2 * (TQ * E) + (oq + i) * E + oe);
            float4 o;
            o.x = oacc[i][0] + r0.x + r1.x + r2.x;
            o.y = oacc[i][1] + r0.y + r1.y + r2.y;
            o.z = oacc[i][2] + r0.z + r1.z + r2.z;
            o.w = oacc[i][3] + r0.w + r1.w + r2.w;
            *(float4*)(og + (oq + i) * E + oe) = o;
        }
    }
}

// ---------------------------------------------------------------------------
extern "C" void kernel_launch(void* const* d_in, const int* in_sizes, int n_in,
                              void* d_out, int out_size) {
    (void)in_sizes; (void)n_in; (void)out_size;
    const float* query = (const float*)d_in[0];
    const float* key   = (const float*)d_in[1];
    const float* value = (const float*)d_in[2];
    const float* Wq    = (const float*)d_in[3];
    const float* bq    = (const float*)d_in[4];
    const float* Wk    = (const float*)d_in[5];
    const float* bk    = (const float*)d_in[6];
    const float* Wv    = (const float*)d_in[7];
    const float* bv    = (const float*)d_in[8];
    float* out = (float*)d_out;

    cudaFuncSetAttribute(attn_kernel, cudaFuncAttributeMaxDynamicSharedMemorySize, SMEM_BYTES);

    dim3 pg((B * S * H) / PROJ_TOK, 3);
    proj_kernel<<<pg, 256>>>(query, key, value, Wq, bq, Wk, bk, Wv, bv);

    dim3 ag(S / TQ, BH);
    attn_kernel<<<ag, 256, SMEM_BYTES>>>(out);
}

// round 3
// speedup vs baseline: 2.0822x; 2.0822x over previous
#include <cuda_runtime.h>
#include <cuda_fp16.h>
#include <stdint.h>

#define B 4
#define S 2048
#define H 8
#define E 64
#define BH (B*H)
#define PAD 72   // smem row stride in halves (16B-aligned, LDSM conflict-free)

// ---------------------------------------------------------------------------
// Device scratch (allocation-free: __device__ globals)
// ---------------------------------------------------------------------------
__device__ __half g_qh[(size_t)BH*S*E];   // fp16 hi of 0.125*Qproj [bh][s][e]
__device__ __half g_ql[(size_t)BH*S*E];   // fp16 lo residual
__device__ __half g_kh[(size_t)BH*S*E];   // fp16 hi of Kproj       [bh][s][e]
__device__ __half g_kl[(size_t)BH*S*E];
__device__ __half g_vh[(size_t)BH*E*S];   // fp16 hi of Vproj, TRANSPOSED [bh][e][s]
__device__ __half g_vl[(size_t)BH*E*S];
__device__ float  g_sc[(size_t)BH*S*S];   // fp32 scores [bh][q][k]
__device__ __half g_at[(size_t)BH*S*S];   // fp16 attn   [bh][q][k]

// ---------------------------------------------------------------------------
// Warp MMA helpers (baseline PTX ISA — works at .target sm_103)
// ---------------------------------------------------------------------------
__device__ __forceinline__ uint32_t smem_to_u32(const void* p) {
    uint32_t a;
    asm("{ .reg .u64 t; cvta.to.shared.u64 t, %1; cvt.u32.u64 %0, t; }" : "=r"(a) : "l"(p));
    return a;
}
#define LDSM_X4(R0, R1, R2, R3, ADDR) \
    asm volatile("ldmatrix.sync.aligned.m8n8.x4.shared.b16 {%0,%1,%2,%3}, [%4];" \
                 : "=r"(R0), "=r"(R1), "=r"(R2), "=r"(R3) : "r"(ADDR))
#define MMA16816(C, A0, A1, A2, A3, B0, B1) \
    asm volatile("mma.sync.aligned.m16n8k16.row.col.f32.f16.f16.f32 " \
                 "{%0,%1,%2,%3}, {%4,%5,%6,%7}, {%8,%9}, {%0,%1,%2,%3};" \
                 : "+f"((C)[0]), "+f"((C)[1]), "+f"((C)[2]), "+f"((C)[3]) \
                 : "r"(A0), "r"(A1), "r"(A2), "r"(A3), "r"(B0), "r"(B1))

// ---------------------------------------------------------------------------
// Threefry2x32 (JAX partitionable): bits(i) = x0^x1 of threefry(key=(0,42),(0,i))
// Validated in Round 1 (rel_err 1.8e-6).
// ---------------------------------------------------------------------------
__device__ __forceinline__ uint32_t rotl32(uint32_t v, int s) { return __funnelshift_l(v, v, s); }
__device__ __forceinline__ uint32_t threefry_mask_bits(uint32_t idx) {
    const uint32_t ks0 = 0u, ks1 = 42u, ks2 = 0x1BD11BDAu ^ 42u;
    uint32_t x0 = ks0, x1 = idx + ks1;
#define TFR(r) { x0 += x1; x1 = rotl32(x1, r); x1 ^= x0; }
    TFR(13) TFR(15) TFR(26) TFR(6)
    x0 += ks1; x1 += ks2 + 1u;
    TFR(17) TFR(29) TFR(16) TFR(24)
    x0 += ks2; x1 += ks0 + 2u;
    TFR(13) TFR(15) TFR(26) TFR(6)
    x0 += ks0; x1 += ks1 + 3u;
    TFR(17) TFR(29) TFR(16) TFR(24)
    x0 += ks1; x1 += ks2 + 4u;
    TFR(13) TFR(15) TFR(26) TFR(6)
    x0 += ks2; x1 += ks0 + 5u;
#undef TFR
    return x0 ^ x1;
}
#define KEEP_THRESH (7549747u << 9)   // bits < this <=> uniform < 0.9f

// ---------------------------------------------------------------------------
// Kernel 1: QKV projection -> fp16 hi/lo (Q scaled 0.125, V transposed)
// ---------------------------------------------------------------------------
#define PROJ_TOK 32

__global__ __launch_bounds__(256) void proj_kernel(
    const float* __restrict__ qin, const float* __restrict__ kin, const float* __restrict__ vin,
    const float* __restrict__ Wq, const float* __restrict__ bq,
    const float* __restrict__ Wk, const float* __restrict__ bk,
    const float* __restrict__ Wv, const float* __restrict__ bv)
{
    __shared__ float sW[64][68];
    __shared__ float sb[64];
    __shared__ float sx[PROJ_TOK][64];

    const int m = blockIdx.y;
    const float* __restrict__ xin  = (m == 0) ? qin : ((m == 1) ? kin : vin);
    const float* __restrict__ W    = (m == 0) ? Wq  : ((m == 1) ? Wk  : Wv);
    const float* __restrict__ bias = (m == 0) ? bq  : ((m == 1) ? bk  : bv);

    const int tid = threadIdx.x;
    const size_t tok0 = (size_t)blockIdx.x * PROJ_TOK;

    for (int i = tid; i < 64 * 16; i += 256) {
        int r = i >> 4, c = i & 15;
        ((float4*)(&sW[r][0]))[c] = ((const float4*)W)[i];
    }
    if (tid < 64) sb[tid] = bias[tid];
    for (int i = tid; i < PROJ_TOK * 16; i += 256)
        ((float4*)(&sx[0][0]))[i] = ((const float4*)(xin + tok0 * 64))[i];
    __syncthreads();

    const int f  = tid & 63;
    const int tg = tid >> 6;

    float4 wr[16];
    #pragma unroll
    for (int e4 = 0; e4 < 16; e4++) wr[e4] = ((float4*)(&sW[f][0]))[e4];
    const float bsv = sb[f];

    for (int tt = 0; tt < PROJ_TOK; tt += 4) {
        const int t = tt + tg;
        float acc = bsv;
        #pragma unroll
        for (int e4 = 0; e4 < 16; e4++) {
            float4 xv = ((float4*)(&sx[t][0]))[e4];
            acc += xv.x * wr[e4].x + xv.y * wr[e4].y + xv.z * wr[e4].z + xv.w * wr[e4].w;
        }
        const size_t tok = tok0 + t;
        const int b   = (int)(tok >> 14);
        const int rem = (int)(tok & 16383);
        const int s   = rem >> 3;
        const int hh  = rem & 7;
        const size_t bh = (size_t)(b * H + hh);

        float a = (m == 0) ? acc * 0.125f : acc;
        __half hi = __float2half_rn(a);
        __half lo = __float2half_rn(a - __half2float(hi));
        if (m == 0) {
            size_t o = (bh * S + s) * 64 + f;
            g_qh[o] = hi; g_ql[o] = lo;
        } else if (m == 1) {
            size_t o = (bh * S + s) * 64 + f;
            g_kh[o] = hi; g_kl[o] = lo;
        } else {
            size_t o = (bh * 64 + f) * S + s;   // transposed
            g_vh[o] = hi; g_vl[o] = lo;
        }
    }
}

// ---------------------------------------------------------------------------
// Kernel 2: scores = (0.125*Q) @ K^T via HMMA, hi/lo split (3 products).
// CTA: 128q x 128k tile; 8 warps = 4(q) x 2(k); warp tile 32q x 64k.
// ---------------------------------------------------------------------------
__global__ __launch_bounds__(256) void scores_kernel()
{
    extern __shared__ char smraw[];
    __half* sQH = (__half*)smraw;          // [128][PAD]
    __half* sQL = sQH + 128 * PAD;
    __half* sKH = sQL + 128 * PAD;
    __half* sKL = sKH + 128 * PAD;

    const int tid = threadIdx.x;
    const int k0 = blockIdx.x * 128, q0 = blockIdx.y * 128, bh = blockIdx.z;

    const __half* qhp = g_qh + ((size_t)bh * S + q0) * 64;
    const __half* qlp = g_ql + ((size_t)bh * S + q0) * 64;
    const __half* khp = g_kh + ((size_t)bh * S + k0) * 64;
    const __half* klp = g_kl + ((size_t)bh * S + k0) * 64;

    for (int i = tid; i < 1024; i += 256) {
        int r = i >> 3, c = (i & 7) * 8;
        *(uint4*)(sQH + r * PAD + c) = *(const uint4*)(qhp + r * 64 + c);
        *(uint4*)(sQL + r * PAD + c) = *(const uint4*)(qlp + r * 64 + c);
        *(uint4*)(sKH + r * PAD + c) = *(const uint4*)(khp + r * 64 + c);
        *(uint4*)(sKL + r * PAD + c) = *(const uint4*)(klp + r * 64 + c);
    }
    __syncthreads();

    const int w = tid >> 5, lane = tid & 31;
    const int qrow0 = (w >> 1) * 32, kcol0 = (w & 1) * 64;
    const int lr = lane & 7, lg = lane >> 3;

    // ldmatrix address components
    const int arow = qrow0 + lr + (lg & 1) * 8;   // + mt*16
    const int acol = (lg >> 1) * 8;               // + ks*16
    const int brow = kcol0 + lr + (lg >> 1) * 8;  // + nbp*16
    const int bcol = (lg & 1) * 8;                // + ks*16

    const uint32_t uQH = smem_to_u32(sQH), uQL = smem_to_u32(sQL);
    const uint32_t uKH = smem_to_u32(sKH), uKL = smem_to_u32(sKL);

    float acc[2][8][4];
    #pragma unroll
    for (int i = 0; i < 2; i++)
        #pragma unroll
        for (int j = 0; j < 8; j++)
            #pragma unroll
            for (int l = 0; l < 4; l++) acc[i][j][l] = 0.0f;

    #pragma unroll
    for (int sp = 0; sp < 3; sp++) {
        const uint32_t uA = (sp < 2) ? uQH : uQL;
        const uint32_t uB = (sp == 1) ? uKL : uKH;
        #pragma unroll
        for (int ks = 0; ks < 4; ks++) {
            uint32_t a[2][4];
            #pragma unroll
            for (int mt = 0; mt < 2; mt++)
                LDSM_X4(a[mt][0], a[mt][1], a[mt][2], a[mt][3],
                        uA + (uint32_t)(((arow + mt * 16) * PAD + acol + ks * 16) * 2));
            uint32_t b[4][4];
            #pragma unroll
            for (int nbp = 0; nbp < 4; nbp++)
                LDSM_X4(b[nbp][0], b[nbp][1], b[nbp][2], b[nbp][3],
                        uB + (uint32_t)(((brow + nbp * 16) * PAD + bcol + ks * 16) * 2));
            #pragma unroll
            for (int mt = 0; mt < 2; mt++)
                #pragma unroll
                for (int nb = 0; nb < 8; nb++)
                    MMA16816(acc[mt][nb], a[mt][0], a[mt][1], a[mt][2], a[mt][3],
                             b[nb >> 1][(nb & 1) * 2], b[nb >> 1][(nb & 1) * 2 + 1]);
        }
    }

    // epilogue: fp32 scores to gmem
    float* dst = g_sc + ((size_t)bh * S + q0 + qrow0) * S + k0 + kcol0;
    const int er = lane >> 2, ec = (lane & 3) * 2;
    #pragma unroll
    for (int mt = 0; mt < 2; mt++)
        #pragma unroll
        for (int nb = 0; nb < 8; nb++) {
            *(float2*)(dst + (size_t)(mt * 16 + er) * S + nb * 8 + ec) =
                make_float2(acc[mt][nb][0], acc[mt][nb][1]);
            *(float2*)(dst + (size_t)(mt * 16 + er + 8) * S + nb * 8 + ec) =
                make_float2(acc[mt][nb][2], acc[mt][nb][3]);
        }
}

// ---------------------------------------------------------------------------
// Kernel 3: softmax + threefry dropout + fp16 round.  Row per warp.
// ---------------------------------------------------------------------------
__global__ __launch_bounds__(256) void softmax_kernel()
{
    extern __shared__ char smraw[];
    float* srow = (float*)smraw;          // 8 rows x 2048
    const int warp = threadIdx.x >> 5, lane = threadIdx.x & 31;
    const size_t row = (size_t)blockIdx.x * 8 + warp;

    const float4* src = (const float4*)(g_sc + row * S);
    float4* my = (float4*)(srow + warp * S);

    float mx = -1e30f;
    #pragma unroll
    for (int j = 0; j < 16; j++) {
        float4 t = src[lane + 32 * j];
        my[lane + 32 * j] = t;
        mx = fmaxf(mx, fmaxf(fmaxf(t.x, t.y), fmaxf(t.z, t.w)));
    }
    #pragma unroll
    for (int o = 16; o; o >>= 1) mx = fmaxf(mx, __shfl_xor_sync(0xffffffffu, mx, o));

    float sum = 0.0f;
    #pragma unroll
    for (int j = 0; j < 16; j++) {
        float4 t = my[lane + 32 * j];
        t.x = expf(t.x - mx); t.y = expf(t.y - mx);
        t.z = expf(t.z - mx); t.w = expf(t.w - mx);
        my[lane + 32 * j] = t;
        sum += t.x + t.y + t.z + t.w;
    }
    #pragma unroll
    for (int o = 16; o; o >>= 1) sum += __shfl_xor_sync(0xffffffffu, sum, o);
    const float inv = 1.0f / sum;
    const float c09 = 1.0f / 0.9f;

    const uint32_t base = (uint32_t)row * (uint32_t)S;
    uint2* dst = (uint2*)(g_at + row * S);
    #pragma unroll 4
    for (int j = 0; j < 16; j++) {
        float4 t = my[lane + 32 * j];
        t.x *= inv; t.y *= inv; t.z *= inv; t.w *= inv;
        const uint32_t i0 = base + 4u * (uint32_t)(lane + 32 * j);
        uint32_t b0 = threefry_mask_bits(i0);
        uint32_t b1 = threefry_mask_bits(i0 + 1u);
        uint32_t b2 = threefry_mask_bits(i0 + 2u);
        uint32_t b3 = threefry_mask_bits(i0 + 3u);
        t.x = (b0 < KEEP_THRESH) ? t.x * c09 : 0.0f;
        t.y = (b1 < KEEP_THRESH) ? t.y * c09 : 0.0f;
        t.z = (b2 < KEEP_THRESH) ? t.z * c09 : 0.0f;
        t.w = (b3 < KEEP_THRESH) ? t.w * c09 : 0.0f;
        uint32_t p0 = (uint32_t)__half_as_ushort(__float2half_rn(t.x)) |
                      ((uint32_t)__half_as_ushort(__float2half_rn(t.y)) << 16);
        uint32_t p1 = (uint32_t)__half_as_ushort(__float2half_rn(t.z)) |
                      ((uint32_t)__half_as_ushort(__float2half_rn(t.w)) << 16);
        dst[lane + 32 * j] = make_uint2(p0, p1);
    }
}

// ---------------------------------------------------------------------------
// Kernel 4: out = attn16 @ V via HMMA.  A exact fp16, V hi/lo split.
// CTA: 128q x 64e; 8 warps = 4(q) x 2(e); warp tile 32q x 32e; K in 32x64 chunks.
// ---------------------------------------------------------------------------
__global__ __launch_bounds__(256) void attnv_kernel(float* __restrict__ out)
{
    extern __shared__ char smraw[];
    __half* sA  = (__half*)smraw;        // [128][PAD]
    __half* sVH = sA + 128 * PAD;        // [64][PAD]
    __half* sVL = sVH + 64 * PAD;

    const int tid = threadIdx.x;
    const int q0 = blockIdx.x * 128, bh = blockIdx.y;

    const __half* at0 = g_at + ((size_t)bh * S + q0) * S;
    const __half* vh0 = g_vh + (size_t)bh * 64 * S;
    const __half* vl0 = g_vl + (size_t)bh * 64 * S;

    const int w = tid >> 5, lane = tid & 31;
    const int qrow0 = (w >> 1) * 32, ecol0 = (w & 1) * 32;
    const int lr = lane & 7, lg = lane >> 3;

    const int arow = qrow0 + lr + (lg & 1) * 8;
    const int acol = (lg >> 1) * 8;
    const int brow = ecol0 + lr + (lg >> 1) * 8;
    const int bcol = (lg & 1) * 8;

    const uint32_t uA  = smem_to_u32(sA);
    const uint32_t uVH = smem_to_u32(sVH);
    const uint32_t uVL = smem_to_u32(sVL);

    float acc[2][4][4];
    #pragma unroll
    for (int i = 0; i < 2; i++)
        #pragma unroll
        for (int j = 0; j < 4; j++)
            #pragma unroll
            for (int l = 0; l < 4; l++) acc[i][j][l] = 0.0f;

    for (int kc = 0; kc < 32; kc++) {
        __syncthreads();
        for (int i = tid; i < 1024; i += 256) {
            int r = i >> 3, c = (i & 7) * 8;
            *(uint4*)(sA + r * PAD + c) = *(const uint4*)(at0 + (size_t)r * S + kc * 64 + c);
        }
        for (int i = tid; i < 512; i += 256) {
            int r = i >> 3, c = (i & 7) * 8;
            *(uint4*)(sVH + r * PAD + c) = *(const uint4*)(vh0 + (size_t)r * S + kc * 64 + c);
            *(uint4*)(sVL + r * PAD + c) = *(const uint4*)(vl0 + (size_t)r * S + kc * 64 + c);
        }
        __syncthreads();

        #pragma unroll
        for (int ks = 0; ks < 4; ks++) {
            uint32_t a[2][4];
            #pragma unroll
            for (int mt = 0; mt < 2; mt++)
                LDSM_X4(a[mt][0], a[mt][1], a[mt][2], a[mt][3],
                        uA + (uint32_t)(((arow + mt * 16) * PAD + acol + ks * 16) * 2));
            uint32_t bhf[2][4], blf[2][4];
            #pragma unroll
            for (int nbp = 0; nbp < 2; nbp++) {
                LDSM_X4(bhf[nbp][0], bhf[nbp][1], bhf[nbp][2], bhf[nbp][3],
                        uVH + (uint32_t)(((brow + nbp * 16) * PAD + bcol + ks * 16) * 2));
                LDSM_X4(blf[nbp][0], blf[nbp][1], blf[nbp][2], blf[nbp][3],
                        uVL + (uint32_t)(((brow + nbp * 16) * PAD + bcol + ks * 16) * 2));
            }
            #pragma unroll
            for (int mt = 0; mt < 2; mt++)
                #pragma unroll
                for (int nb = 0; nb < 4; nb++) {
                    MMA16816(acc[mt][nb], a[mt][0], a[mt][1], a[mt][2], a[mt][3],
                             bhf[nb >> 1][(nb & 1) * 2], bhf[nb >> 1][(nb & 1) * 2 + 1]);
                    MMA16816(acc[mt][nb], a[mt][0], a[mt][1], a[mt][2], a[mt][3],
                             blf[nb >> 1][(nb & 1) * 2], blf[nb >> 1][(nb & 1) * 2 + 1]);
                }
        }
    }

    float* dst = out + ((size_t)bh * S + q0 + qrow0) * 64 + ecol0;
    const int er = lane >> 2, ec = (lane & 3) * 2;
    #pragma unroll
    for (int mt = 0; mt < 2; mt++)
        #pragma unroll
        for (int nb = 0; nb < 4; nb++) {
            *(float2*)(dst + (size_t)(mt * 16 + er) * 64 + nb * 8 + ec) =
                make_float2(acc[mt][nb][0], acc[mt][nb][1]);
            *(float2*)(dst + (size_t)(mt * 16 + er + 8) * 64 + nb * 8 + ec) =
                make_float2(acc[mt][nb][2], acc[mt][nb][3]);
        }
}

// ---------------------------------------------------------------------------
extern "C" void kernel_launch(void* const* d_in, const int* in_sizes, int n_in,
                              void* d_out, int out_size) {
    (void)in_sizes; (void)n_in; (void)out_size;
    const float* query = (const float*)d_in[0];
    const float* key   = (const float*)d_in[1];
    const float* value = (const float*)d_in[2];
    const float* Wq    = (const float*)d_in[3];
    const float* bq    = (const float*)d_in[4];
    const float* Wk    = (const float*)d_in[5];
    const float* bk    = (const float*)d_in[6];
    const float* Wv    = (const float*)d_in[7];
    const float* bv    = (const float*)d_in[8];
    float* out = (float*)d_out;

    const int sc_smem = 4 * 128 * PAD * 2;            // 73728
    const int sm_smem = 8 * S * 4;                    // 65536
    const int av_smem = (128 + 64 + 64) * PAD * 2;    // 36864

    cudaFuncSetAttribute(scores_kernel,  cudaFuncAttributeMaxDynamicSharedMemorySize, sc_smem);
    cudaFuncSetAttribute(softmax_kernel, cudaFuncAttributeMaxDynamicSharedMemorySize, sm_smem);
    cudaFuncSetAttribute(attnv_kernel,   cudaFuncAttributeMaxDynamicSharedMemorySize, av_smem);

    dim3 pg((B * S * H) / PROJ_TOK, 3);
    proj_kernel<<<pg, 256>>>(query, key, value, Wq, bq, Wk, bk, Wv, bv);

    dim3 sg(S / 128, S / 128, BH);
    scores_kernel<<<sg, 256, sc_smem>>>();

    softmax_kernel<<<(BH * S) / 8, 256, sm_smem>>>();

    dim3 ag(S / 128, BH);
    attnv_kernel<<<ag, 256, av_smem>>>(out);
}